// round 1
// baseline (speedup 1.0000x reference)
#include <cuda_runtime.h>
#include <math.h>
#include <stddef.h>

// ---------------------------------------------------------------------------
// Problem constants
// ---------------------------------------------------------------------------
#define Bn   16
#define NT   1025            // tokens (1 cls + 1024 patches)
#define Cd   768
#define Hh   12
#define Dd   64
#define NP   1024            // patch tokens
#define Ll   256             // landmarks (16x16)
#define BH   (Bn*Hh)         // 192
#define NEWTON_ITERS 6
// tau = sqrt(64) = 8  ->  multiply dist by -1/8
#define NEG_INV_TAU (-0.125f)

// ---------------------------------------------------------------------------
// Scratch (static device globals; allocation at module load, allowed)
// ---------------------------------------------------------------------------
__device__ float g_q[BH * NT * Dd];
__device__ float g_k[BH * NT * Dd];
__device__ float g_v[BH * NT * Dd];
__device__ float g_qland[BH * Ll * Dd];
__device__ float g_kland[BH * Ll * Dd];
__device__ float g_qpn[BH * NP];
__device__ float g_kpn[BH * NP];
__device__ float g_qln[BH * Ll];
__device__ float g_kln[BH * Ll];
__device__ float g_qcn[BH];
__device__ float g_M1[(size_t)BH * NP * Ll];
__device__ float g_M2[(size_t)BH * Ll * Ll];
__device__ float g_M3[(size_t)BH * Ll * NP];
__device__ float g_invA[(size_t)BH * Ll * Ll];
__device__ float g_invB[(size_t)BH * Ll * Ll];
__device__ float g_T[(size_t)BH * Ll * Ll];
__device__ float g_KV[BH * Ll * Dd];
__device__ float g_Vmix[BH * Ll * Dd];
__device__ float g_attn[(size_t)Bn * NT * Cd];

// ---------------------------------------------------------------------------
// Epilogue functors
// ---------------------------------------------------------------------------
struct EpiQKV {
    const float* bias;
    __device__ __forceinline__ void store(int, int m, int j, float acc) const {
        int b = m / NT, n = m % NT;
        int part = j / Cd;
        int rem  = j % Cd;
        int h = rem / Dd, d = rem % Dd;
        float* dst = (part == 0) ? g_q : ((part == 1) ? g_k : g_v);
        dst[(((size_t)b * Hh + h) * NT + n) * Dd + d] = acc + bias[j];
    }
};

struct EpiGauss {
    const float* xn; const float* yn; float* out;
    int sxn; int syn; int ldc; size_t sout;
    __device__ __forceinline__ void store(int bh, int m, int n, float acc) const {
        float dist = xn[(size_t)bh * sxn + m] + yn[(size_t)bh * syn + n] - 2.0f * acc;
        out[(size_t)bh * sout + (size_t)m * ldc + n] = expf(dist * NEG_INV_TAU);
    }
};

struct EpiPlain {
    float* out; int ldc; size_t s;
    __device__ __forceinline__ void store(int bh, int m, int n, float acc) const {
        out[(size_t)bh * s + (size_t)m * ldc + n] = acc;
    }
};

struct EpiNewton {   // out = 2*inv - acc   (inv @ (2I - M@inv) = 2*inv - inv@T)
    const float* inv; float* out;
    __device__ __forceinline__ void store(int bh, int m, int n, float acc) const {
        size_t off = ((size_t)bh * Ll + m) * Ll + n;
        out[off] = 2.0f * inv[off] - acc;
    }
};

struct EpiYPatch {   // write into attn layout [b][n=m+1][h*64+j]
    __device__ __forceinline__ void store(int bh, int m, int j, float acc) const {
        int b = bh / Hh, h = bh % Hh;
        g_attn[((size_t)b * NT + (m + 1)) * Cd + h * Dd + j] = acc;
    }
};

struct EpiProj {
    const float* bias; float* out;
    __device__ __forceinline__ void store(int, int m, int j, float acc) const {
        out[(size_t)m * Cd + j] = acc + bias[j];
    }
};

// ---------------------------------------------------------------------------
// Generic tiled SGEMM.  C_tile = A(MxK, row-major, lda) @ op(B)
//   BT=true : B is [N x K] row-major (C = A @ B^T)
//   BT=false: B is [K x N] row-major (C = A @ B)
// Batched via blockIdx.z with strides sA/sB. Epilogue does all stores.
// Requires K % 16 == 0, lda/ldb % 4 == 0, N tiles full (N % BN == 0 here).
// ---------------------------------------------------------------------------
template<int BM, int BN, int TM, int TN, bool BT, class Epi>
__global__ __launch_bounds__(256)
void gemm_k(const float* __restrict__ A, const float* __restrict__ Bp,
            int M, int Nn, int K, int lda, int ldb,
            size_t sA, size_t sB, Epi epi)
{
    constexpr int BK = 16;
    static_assert((BM / TM) * (BN / TN) == 256, "thread count");
    const int bh = blockIdx.z;
    A  += (size_t)bh * sA;
    Bp += (size_t)bh * sB;
    const int m0 = blockIdx.y * BM;
    const int n0 = blockIdx.x * BN;
    const int tid = threadIdx.x;
    const int tx = tid % (BN / TN);
    const int ty = tid / (BN / TN);

    __shared__ float As[BK][BM];
    __shared__ float Bs[BK][BN];

    float acc[TM][TN];
#pragma unroll
    for (int i = 0; i < TM; i++)
#pragma unroll
        for (int j = 0; j < TN; j++) acc[i][j] = 0.0f;

    for (int k0 = 0; k0 < K; k0 += BK) {
        // ---- load A tile (transpose into As[k][m]) ----
        constexpr int AV = BM * BK / (256 * 4);
#pragma unroll
        for (int t = 0; t < AV; t++) {
            int i  = tid + t * 256;
            int m  = i / (BK / 4);
            int kq = i % (BK / 4);
            float4 val = make_float4(0.f, 0.f, 0.f, 0.f);
            if (m0 + m < M)
                val = *(const float4*)&A[(size_t)(m0 + m) * lda + k0 + kq * 4];
            As[kq * 4 + 0][m] = val.x;
            As[kq * 4 + 1][m] = val.y;
            As[kq * 4 + 2][m] = val.z;
            As[kq * 4 + 3][m] = val.w;
        }
        // ---- load B tile ----
        if (BT) {
            constexpr int BV = BN * BK / (256 * 4);
#pragma unroll
            for (int t = 0; t < BV; t++) {
                int i  = tid + t * 256;
                int n  = i / (BK / 4);
                int kq = i % (BK / 4);
                float4 val = make_float4(0.f, 0.f, 0.f, 0.f);
                if (n0 + n < Nn)
                    val = *(const float4*)&Bp[(size_t)(n0 + n) * ldb + k0 + kq * 4];
                Bs[kq * 4 + 0][n] = val.x;
                Bs[kq * 4 + 1][n] = val.y;
                Bs[kq * 4 + 2][n] = val.z;
                Bs[kq * 4 + 3][n] = val.w;
            }
        } else {
            constexpr int BV = BN * BK / (256 * 4);
#pragma unroll
            for (int t = 0; t < BV; t++) {
                int i  = tid + t * 256;
                int kk = i / (BN / 4);
                int nq = i % (BN / 4);
                float4 val = *(const float4*)&Bp[(size_t)(k0 + kk) * ldb + n0 + nq * 4];
                *(float4*)&Bs[kk][nq * 4] = val;
            }
        }
        __syncthreads();

#pragma unroll
        for (int kk = 0; kk < BK; kk++) {
            float a[TM], bfrag[TN];
#pragma unroll
            for (int vv = 0; vv < TM / 4; vv++)
                *(float4*)&a[vv * 4] = *(const float4*)&As[kk][ty * TM + vv * 4];
#pragma unroll
            for (int vv = 0; vv < TN / 4; vv++)
                *(float4*)&bfrag[vv * 4] = *(const float4*)&Bs[kk][tx * TN + vv * 4];
#pragma unroll
            for (int i = 0; i < TM; i++)
#pragma unroll
                for (int j = 0; j < TN; j++)
                    acc[i][j] += a[i] * bfrag[j];
        }
        __syncthreads();
    }

#pragma unroll
    for (int i = 0; i < TM; i++) {
        int gm = m0 + ty * TM + i;
        if (gm >= M) continue;
#pragma unroll
        for (int j = 0; j < TN; j++) {
            int gn = n0 + tx * TN + j;
            if (gn < Nn) epi.store(bh, gm, gn, acc[i][j]);
        }
    }
}

// ---------------------------------------------------------------------------
// Small helper kernels
// ---------------------------------------------------------------------------

// 2x2 mean pool of q_patch / k_patch -> landmarks. One thread per (bh,l,d).
__global__ void pool_kernel()
{
    int idx = blockIdx.x * blockDim.x + threadIdx.x;
    if (idx >= BH * Ll * Dd) return;
    int d  = idx % Dd;
    int l  = (idx / Dd) % Ll;
    int bh = idx / (Dd * Ll);
    int lr = l / 16, lc = l % 16;
    float sq = 0.f, sk = 0.f;
#pragma unroll
    for (int r = 0; r < 2; r++)
#pragma unroll
        for (int c = 0; c < 2; c++) {
            int p = (2 * lr + r) * 32 + (2 * lc + c);
            size_t off = ((size_t)bh * NT + (p + 1)) * Dd + d;
            sq += g_q[off];
            sk += g_k[off];
        }
    g_qland[((size_t)bh * Ll + l) * Dd + d] = sq * 0.25f;
    g_kland[((size_t)bh * Ll + l) * Dd + d] = sk * 0.25f;
}

__device__ __forceinline__ float row_sq_norm(const float* p)
{
    const float4* p4 = (const float4*)p;
    float s = 0.f;
#pragma unroll
    for (int i = 0; i < Dd / 4; i++) {
        float4 v = p4[i];
        s += v.x * v.x + v.y * v.y + v.z * v.z + v.w * v.w;
    }
    return s;
}

// squared norms of q_patch / k_patch rows
__global__ void norms_patch_kernel()
{
    int idx = blockIdx.x * blockDim.x + threadIdx.x;
    if (idx >= BH * NP) return;
    int bh = idx / NP, p = idx % NP;
    size_t off = ((size_t)bh * NT + (p + 1)) * Dd;
    g_qpn[idx] = row_sq_norm(&g_q[off]);
    g_kpn[idx] = row_sq_norm(&g_k[off]);
}

// squared norms of landmarks + cls query norm
__global__ void norms_land_kernel()
{
    int idx = blockIdx.x * blockDim.x + threadIdx.x;
    if (idx >= BH * Ll) return;
    g_qln[idx] = row_sq_norm(&g_qland[(size_t)idx * Dd]);
    g_kln[idx] = row_sq_norm(&g_kland[(size_t)idx * Dd]);
    if (idx < BH)
        g_qcn[idx] = row_sq_norm(&g_q[(size_t)idx * NT * Dd]);  // n = 0 (cls)
}

// Newton init: inv0 = M2^T / (norm_inf^2 + 1e-6), one block per batch
__global__ void newton_init_kernel()
{
    int bh = blockIdx.x;
    int t  = threadIdx.x;        // 256 threads, one row each
    const float* M2b = g_M2 + (size_t)bh * Ll * Ll;
    const float* row = M2b + (size_t)t * Ll;
    float rs = 0.f;
    for (int j = 0; j < Ll; j++) rs += fabsf(row[j]);
    __shared__ float red[256];
    red[t] = rs;
    __syncthreads();
    for (int s = 128; s > 0; s >>= 1) {
        if (t < s) red[t] = fmaxf(red[t], red[t + s]);
        __syncthreads();
    }
    float nrm = red[0];
    float scale = 1.0f / (nrm * nrm + 1e-6f);
    float* inv = g_invA + (size_t)bh * Ll * Ll;
    for (int idx = t; idx < Ll * Ll; idx += 256) {
        int i = idx / Ll, j = idx % Ll;
        inv[idx] = M2b[(size_t)j * Ll + i] * scale;
    }
}

// cls row: scores vs landmarks, then @ V_mixed. One block per bh.
__global__ void ycls_kernel()
{
    int bh = blockIdx.x;
    int t  = threadIdx.x;        // 256 threads
    __shared__ float sc[Ll];
    __shared__ float qc[Dd];
    if (t < Dd) qc[t] = g_q[(size_t)bh * NT * Dd + t];
    __syncthreads();
    const float* kl = g_kland + ((size_t)bh * Ll + t) * Dd;
    float dot = 0.f;
#pragma unroll
    for (int d = 0; d < Dd; d++) dot += qc[d] * kl[d];
    float dist = g_qcn[bh] + g_kln[(size_t)bh * Ll + t] - 2.0f * dot;
    sc[t] = expf(dist * NEG_INV_TAU);
    __syncthreads();
    if (t < Dd) {
        float s = 0.f;
        for (int l = 0; l < Ll; l++)
            s += sc[l] * g_Vmix[((size_t)bh * Ll + l) * Dd + t];
        int b = bh / Hh, h = bh % Hh;
        g_attn[(size_t)b * NT * Cd + h * Dd + t] = s;
    }
}

// ---------------------------------------------------------------------------
// Host launcher
// ---------------------------------------------------------------------------
extern "C" void kernel_launch(void* const* d_in, const int* in_sizes, int n_in,
                              void* d_out, int out_size)
{
    (void)in_sizes; (void)n_in; (void)out_size;
    const float* x      = (const float*)d_in[0];
    const float* qkv_w  = (const float*)d_in[1];
    const float* qkv_b  = (const float*)d_in[2];
    const float* proj_w = (const float*)d_in[3];
    const float* proj_b = (const float*)d_in[4];
    float* out = (float*)d_out;

    float *p_q, *p_k, *p_v, *p_qland, *p_kland;
    float *p_qpn, *p_kpn, *p_qln, *p_kln;
    float *p_M1, *p_M2, *p_M3, *p_invA, *p_invB, *p_T, *p_KV, *p_Vmix, *p_attn;
    cudaGetSymbolAddress((void**)&p_q, g_q);
    cudaGetSymbolAddress((void**)&p_k, g_k);
    cudaGetSymbolAddress((void**)&p_v, g_v);
    cudaGetSymbolAddress((void**)&p_qland, g_qland);
    cudaGetSymbolAddress((void**)&p_kland, g_kland);
    cudaGetSymbolAddress((void**)&p_qpn, g_qpn);
    cudaGetSymbolAddress((void**)&p_kpn, g_kpn);
    cudaGetSymbolAddress((void**)&p_qln, g_qln);
    cudaGetSymbolAddress((void**)&p_kln, g_kln);
    cudaGetSymbolAddress((void**)&p_M1, g_M1);
    cudaGetSymbolAddress((void**)&p_M2, g_M2);
    cudaGetSymbolAddress((void**)&p_M3, g_M3);
    cudaGetSymbolAddress((void**)&p_invA, g_invA);
    cudaGetSymbolAddress((void**)&p_invB, g_invB);
    cudaGetSymbolAddress((void**)&p_T, g_T);
    cudaGetSymbolAddress((void**)&p_KV, g_KV);
    cudaGetSymbolAddress((void**)&p_Vmix, g_Vmix);
    cudaGetSymbolAddress((void**)&p_attn, g_attn);

    const int M_tok = Bn * NT;   // 16400

    // 1. QKV projection: x @ qkv_w^T + b, scattered into q/k/v [B][H][N][D]
    {
        EpiQKV epi{qkv_b};
        dim3 grid(3 * Cd / 128, (M_tok + 127) / 128, 1);
        gemm_k<128, 128, 8, 8, true><<<grid, 256>>>(
            x, qkv_w, M_tok, 3 * Cd, Cd, Cd, Cd, 0, 0, epi);
    }

    // 2. pooling + norms
    pool_kernel<<<(BH * Ll * Dd + 255) / 256, 256>>>();
    norms_patch_kernel<<<(BH * NP + 255) / 256, 256>>>();
    norms_land_kernel<<<(BH * Ll + 255) / 256, 256>>>();

    // 3. Gauss kernel matrices
    {   // M2 = gauss(q_land, k_land): [L x L]
        EpiGauss epi{p_qln, p_kln, p_M2, Ll, Ll, Ll, (size_t)Ll * Ll};
        dim3 grid(Ll / 128, Ll / 128, BH);
        gemm_k<128, 128, 8, 8, true><<<grid, 256>>>(
            p_qland, p_kland, Ll, Ll, Dd, Dd, Dd,
            (size_t)Ll * Dd, (size_t)Ll * Dd, epi);
    }
    {   // M1 = gauss(q_patch, k_land): [NP x L]
        EpiGauss epi{p_qpn, p_kln, p_M1, NP, Ll, Ll, (size_t)NP * Ll};
        dim3 grid(Ll / 128, NP / 128, BH);
        gemm_k<128, 128, 8, 8, true><<<grid, 256>>>(
            p_q + Dd, p_kland, NP, Ll, Dd, Dd, Dd,
            (size_t)NT * Dd, (size_t)Ll * Dd, epi);
    }
    {   // M3 = gauss(q_land, k_patch): [L x NP]
        EpiGauss epi{p_qln, p_kpn, p_M3, Ll, NP, NP, (size_t)Ll * NP};
        dim3 grid(NP / 128, Ll / 128, BH);
        gemm_k<128, 128, 8, 8, true><<<grid, 256>>>(
            p_qland, p_k + Dd, Ll, NP, Dd, Dd, Dd,
            (size_t)Ll * Dd, (size_t)NT * Dd, epi);
    }

    // 4. Newton iterations for M2^-1
    newton_init_kernel<<<BH, 256>>>();
    {
        float* cur = p_invA;
        float* nxt = p_invB;
        dim3 grid(Ll / 128, Ll / 128, BH);
        for (int it = 0; it < NEWTON_ITERS; it++) {
            EpiPlain epiT{p_T, Ll, (size_t)Ll * Ll};
            gemm_k<128, 128, 8, 8, false><<<grid, 256>>>(
                p_M2, cur, Ll, Ll, Ll, Ll, Ll,
                (size_t)Ll * Ll, (size_t)Ll * Ll, epiT);
            EpiNewton epiN{cur, nxt};
            gemm_k<128, 128, 8, 8, false><<<grid, 256>>>(
                cur, p_T, Ll, Ll, Ll, Ll, Ll,
                (size_t)Ll * Ll, (size_t)Ll * Ll, epiN);
            float* tmp = cur; cur = nxt; nxt = tmp;
        }
        // NEWTON_ITERS even -> result in p_invA
    }

    // 5. KV = M3 @ v_patch : [L x D]
    {
        EpiPlain epi{p_KV, Dd, (size_t)Ll * Dd};
        dim3 grid(1, Ll / 64, BH);
        gemm_k<64, 64, 4, 4, false><<<grid, 256>>>(
            p_M3, p_v + Dd, Ll, Dd, NP, NP, Dd,
            (size_t)Ll * NP, (size_t)NT * Dd, epi);
    }
    // 6. V_mixed = M2_inv @ KV : [L x D]
    {
        EpiPlain epi{p_Vmix, Dd, (size_t)Ll * Dd};
        dim3 grid(1, Ll / 64, BH);
        gemm_k<64, 64, 4, 4, false><<<grid, 256>>>(
            p_invA, p_KV, Ll, Dd, Ll, Ll, Dd,
            (size_t)Ll * Ll, (size_t)Ll * Dd, epi);
    }
    // 7. y_patch = M1 @ V_mixed -> attn[b][1..1024][h*64+d]
    {
        EpiYPatch epi{};
        dim3 grid(1, NP / 64, BH);
        gemm_k<64, 64, 4, 4, false><<<grid, 256>>>(
            p_M1, p_Vmix, NP, Dd, Ll, Ll, Dd,
            (size_t)NP * Ll, (size_t)Ll * Dd, epi);
    }
    // 8. y_cls -> attn[b][0][h*64+d]
    ycls_kernel<<<BH, 256>>>();

    // 9. output projection: attn @ proj_w^T + proj_b
    {
        EpiProj epi{proj_b, out};
        dim3 grid(Cd / 128, (M_tok + 127) / 128, 1);
        gemm_k<128, 128, 8, 8, true><<<grid, 256>>>(
            p_attn, proj_w, M_tok, Cd, Cd, Cd, Cd, 0, 0, epi);
    }
}

// round 2
// speedup vs baseline: 2.3069x; 2.3069x over previous
#include <cuda_runtime.h>
#include <math.h>
#include <stddef.h>

// ---------------------------------------------------------------------------
// Problem constants
// ---------------------------------------------------------------------------
#define Bn   16
#define NT   1025            // tokens (1 cls + 1024 patches)
#define Cd   768
#define Hh   12
#define Dd   64
#define NP   1024            // patch tokens
#define Ll   256             // landmarks (16x16)
#define BH   (Bn*Hh)         // 192
#define NEWTON_ITERS 6
// tau = sqrt(64) = 8  ->  multiply dist by -1/8
#define NEG_INV_TAU (-0.125f)

// ---------------------------------------------------------------------------
// Scratch (static device globals)
// ---------------------------------------------------------------------------
__device__ float g_q[BH * NT * Dd];
__device__ float g_k[BH * NT * Dd];
__device__ float g_v[BH * NT * Dd];
__device__ float g_qland[BH * Ll * Dd];
__device__ float g_kland[BH * Ll * Dd];
__device__ float g_qpn[BH * NP];
__device__ float g_kpn[BH * NP];
__device__ float g_qln[BH * Ll];
__device__ float g_kln[BH * Ll];
__device__ float g_qcn[BH];
__device__ float g_M1[(size_t)BH * NP * Ll];
__device__ float g_M2[(size_t)BH * Ll * Ll];
__device__ float g_M3[(size_t)BH * Ll * NP];
__device__ float g_invA[(size_t)BH * Ll * Ll];
__device__ float g_invB[(size_t)BH * Ll * Ll];
__device__ float g_T[(size_t)BH * Ll * Ll];
__device__ float g_KV[BH * Ll * Dd];
__device__ float g_Vmix[BH * Ll * Dd];
__device__ float g_attn[(size_t)Bn * NT * Cd];

// ---------------------------------------------------------------------------
// Epilogue functors
// ---------------------------------------------------------------------------
struct EpiQKV {
    const float* bias;
    __device__ __forceinline__ void store(int, int m, int j, float acc) const {
        int b = m / NT, n = m % NT;
        int part = j / Cd;
        int rem  = j % Cd;
        int h = rem / Dd, d = rem % Dd;
        float* dst = (part == 0) ? g_q : ((part == 1) ? g_k : g_v);
        dst[(((size_t)b * Hh + h) * NT + n) * Dd + d] = acc + bias[j];
    }
};

struct EpiGauss {
    const float* xn; const float* yn; float* out;
    int sxn; int syn; int ldc; size_t sout;
    __device__ __forceinline__ void store(int bh, int m, int n, float acc) const {
        float dist = xn[(size_t)bh * sxn + m] + yn[(size_t)bh * syn + n] - 2.0f * acc;
        out[(size_t)bh * sout + (size_t)m * ldc + n] = expf(dist * NEG_INV_TAU);
    }
};

struct EpiPlain {
    float* out; int ldc; size_t s;
    __device__ __forceinline__ void store(int bh, int m, int n, float acc) const {
        out[(size_t)bh * s + (size_t)m * ldc + n] = acc;
    }
};

struct EpiNewton {   // out = 2*inv - acc   (inv @ (2I - M@inv) = 2*inv - inv@T)
    const float* inv; float* out;
    __device__ __forceinline__ void store(int bh, int m, int n, float acc) const {
        size_t off = ((size_t)bh * Ll + m) * Ll + n;
        out[off] = 2.0f * inv[off] - acc;
    }
};

struct EpiYPatch {   // write into attn layout [b][n=m+1][h*64+j]
    __device__ __forceinline__ void store(int bh, int m, int j, float acc) const {
        int b = bh / Hh, h = bh % Hh;
        g_attn[((size_t)b * NT + (m + 1)) * Cd + h * Dd + j] = acc;
    }
};

struct EpiProj {
    const float* bias; float* out;
    __device__ __forceinline__ void store(int, int m, int j, float acc) const {
        out[(size_t)m * Cd + j] = acc + bias[j];
    }
};

// ---------------------------------------------------------------------------
// TF32 helpers
// ---------------------------------------------------------------------------
__device__ __forceinline__ unsigned f2t(float f) {
    unsigned u;
    asm("cvt.rna.tf32.f32 %0, %1;" : "=r"(u) : "f"(f));
    return u;
}

__device__ __forceinline__ void mma_tf32(float* c, const unsigned* a, const unsigned* b) {
    asm volatile(
        "mma.sync.aligned.m16n8k8.row.col.f32.tf32.tf32.f32 "
        "{%0,%1,%2,%3}, {%4,%5,%6,%7}, {%8,%9}, {%0,%1,%2,%3};"
        : "+f"(c[0]), "+f"(c[1]), "+f"(c[2]), "+f"(c[3])
        : "r"(a[0]), "r"(a[1]), "r"(a[2]), "r"(a[3]), "r"(b[0]), "r"(b[1]));
}

// ---------------------------------------------------------------------------
// TF32 tensor-core GEMM.  C = A(MxK, row-major, lda) @ op(B)
//   BT=true : B is [N x K] row-major (C = A @ B^T)
//   BT=false: B is [K x N] row-major (C = A @ B)
// Batched via blockIdx.z (strides sA/sB). Warp tile 64x32 of m16n8k8 mmas.
// Requires: K % 32 == 0, Nn % BN == 0, lda/ldb % 4 == 0. M may be ragged.
// ---------------------------------------------------------------------------
template<int BM, int BN, bool BT, class Epi>
__global__ void __launch_bounds__((BM / 64) * (BN / 32) * 32)
gemm_tc(const float* __restrict__ A, const float* __restrict__ Bp,
        int M, int Nn, int K, int lda, int ldb,
        size_t sA, size_t sB, Epi epi)
{
    constexpr int BK = 32;
    constexpr int WARPS_M = BM / 64;
    constexpr int WARPS_N = BN / 32;
    constexpr int THREADS = WARPS_M * WARPS_N * 32;
    constexpr int SA  = BK + 4;     // As stride (units: unsigned)   -> conflict-free
    constexpr int SBT = BK + 4;     // Bs stride, BT layout  [BN][SBT]
    constexpr int SBN = BN + 8;     // Bs stride, non-BT     [BK][SBN]

    __shared__ unsigned As[BM * SA];
    __shared__ unsigned Bs[BT ? (BN * SBT) : (BK * SBN)];

    const int bh = blockIdx.z;
    A  += (size_t)bh * sA;
    Bp += (size_t)bh * sB;
    const int m0 = blockIdx.y * BM;
    const int n0 = blockIdx.x * BN;
    const int tid  = threadIdx.x;
    const int lane = tid & 31;
    const int warp = tid >> 5;
    const int wm = warp / WARPS_N;
    const int wn = warp % WARPS_N;
    const int gid = lane >> 2;      // 0..7
    const int tig = lane & 3;       // 0..3

    float acc[4][4][4];
#pragma unroll
    for (int i = 0; i < 4; i++)
#pragma unroll
        for (int j = 0; j < 4; j++)
#pragma unroll
            for (int r = 0; r < 4; r++) acc[i][j][r] = 0.0f;

    for (int k0 = 0; k0 < K; k0 += BK) {
        // ---- A tile -> As[m][k], tf32 ----
#pragma unroll
        for (int t = 0; t < (BM * 8) / THREADS; t++) {
            int i  = tid + t * THREADS;
            int m  = i >> 3;
            int kq = i & 7;
            float4 v = make_float4(0.f, 0.f, 0.f, 0.f);
            if (m0 + m < M)
                v = *(const float4*)&A[(size_t)(m0 + m) * lda + k0 + kq * 4];
            uint4 u = make_uint4(f2t(v.x), f2t(v.y), f2t(v.z), f2t(v.w));
            *(uint4*)&As[m * SA + kq * 4] = u;
        }
        // ---- B tile ----
        if (BT) {   // B [N x K] -> Bs[n][k]
#pragma unroll
            for (int t = 0; t < (BN * 8) / THREADS; t++) {
                int i  = tid + t * THREADS;
                int n  = i >> 3;
                int kq = i & 7;
                float4 v = *(const float4*)&Bp[(size_t)(n0 + n) * ldb + k0 + kq * 4];
                uint4 u = make_uint4(f2t(v.x), f2t(v.y), f2t(v.z), f2t(v.w));
                *(uint4*)&Bs[n * SBT + kq * 4] = u;
            }
        } else {    // B [K x N] -> Bs[k][n]
#pragma unroll
            for (int t = 0; t < (8 * BN) / THREADS; t++) {
                int i  = tid + t * THREADS;
                int kk = i / (BN / 4);
                int nq = i % (BN / 4);
                float4 v = *(const float4*)&Bp[(size_t)(k0 + kk) * ldb + n0 + nq * 4];
                uint4 u = make_uint4(f2t(v.x), f2t(v.y), f2t(v.z), f2t(v.w));
                *(uint4*)&Bs[kk * SBN + nq * 4] = u;
            }
        }
        __syncthreads();

#pragma unroll
        for (int kk = 0; kk < BK; kk += 8) {
            unsigned af[4][4], bf[4][2];
#pragma unroll
            for (int i = 0; i < 4; i++) {
                int r0 = wm * 64 + i * 16 + gid;
                af[i][0] = As[r0 * SA + kk + tig];
                af[i][1] = As[(r0 + 8) * SA + kk + tig];
                af[i][2] = As[r0 * SA + kk + tig + 4];
                af[i][3] = As[(r0 + 8) * SA + kk + tig + 4];
            }
#pragma unroll
            for (int j = 0; j < 4; j++) {
                int c0 = wn * 32 + j * 8 + gid;
                if (BT) {
                    bf[j][0] = Bs[c0 * SBT + kk + tig];
                    bf[j][1] = Bs[c0 * SBT + kk + tig + 4];
                } else {
                    bf[j][0] = Bs[(kk + tig) * SBN + c0];
                    bf[j][1] = Bs[(kk + tig + 4) * SBN + c0];
                }
            }
#pragma unroll
            for (int i = 0; i < 4; i++)
#pragma unroll
                for (int j = 0; j < 4; j++)
                    mma_tf32(acc[i][j], af[i], bf[j]);
        }
        __syncthreads();
    }

    // ---- epilogue (N is always an exact multiple of BN; only M ragged) ----
#pragma unroll
    for (int i = 0; i < 4; i++) {
        int rm = m0 + wm * 64 + i * 16 + gid;
#pragma unroll
        for (int j = 0; j < 4; j++) {
            int cn = n0 + wn * 32 + j * 8 + tig * 2;
            if (rm < M) {
                epi.store(bh, rm, cn,     acc[i][j][0]);
                epi.store(bh, rm, cn + 1, acc[i][j][1]);
            }
            if (rm + 8 < M) {
                epi.store(bh, rm + 8, cn,     acc[i][j][2]);
                epi.store(bh, rm + 8, cn + 1, acc[i][j][3]);
            }
        }
    }
}

// ---------------------------------------------------------------------------
// Small helper kernels (unchanged from Round 1)
// ---------------------------------------------------------------------------
__global__ void pool_kernel()
{
    int idx = blockIdx.x * blockDim.x + threadIdx.x;
    if (idx >= BH * Ll * Dd) return;
    int d  = idx % Dd;
    int l  = (idx / Dd) % Ll;
    int bh = idx / (Dd * Ll);
    int lr = l / 16, lc = l % 16;
    float sq = 0.f, sk = 0.f;
#pragma unroll
    for (int r = 0; r < 2; r++)
#pragma unroll
        for (int c = 0; c < 2; c++) {
            int p = (2 * lr + r) * 32 + (2 * lc + c);
            size_t off = ((size_t)bh * NT + (p + 1)) * Dd + d;
            sq += g_q[off];
            sk += g_k[off];
        }
    g_qland[((size_t)bh * Ll + l) * Dd + d] = sq * 0.25f;
    g_kland[((size_t)bh * Ll + l) * Dd + d] = sk * 0.25f;
}

__device__ __forceinline__ float row_sq_norm(const float* p)
{
    const float4* p4 = (const float4*)p;
    float s = 0.f;
#pragma unroll
    for (int i = 0; i < Dd / 4; i++) {
        float4 v = p4[i];
        s += v.x * v.x + v.y * v.y + v.z * v.z + v.w * v.w;
    }
    return s;
}

__global__ void norms_patch_kernel()
{
    int idx = blockIdx.x * blockDim.x + threadIdx.x;
    if (idx >= BH * NP) return;
    int bh = idx / NP, p = idx % NP;
    size_t off = ((size_t)bh * NT + (p + 1)) * Dd;
    g_qpn[idx] = row_sq_norm(&g_q[off]);
    g_kpn[idx] = row_sq_norm(&g_k[off]);
}

__global__ void norms_land_kernel()
{
    int idx = blockIdx.x * blockDim.x + threadIdx.x;
    if (idx >= BH * Ll) return;
    g_qln[idx] = row_sq_norm(&g_qland[(size_t)idx * Dd]);
    g_kln[idx] = row_sq_norm(&g_kland[(size_t)idx * Dd]);
    if (idx < BH)
        g_qcn[idx] = row_sq_norm(&g_q[(size_t)idx * NT * Dd]);  // n = 0 (cls)
}

__global__ void newton_init_kernel()
{
    int bh = blockIdx.x;
    int t  = threadIdx.x;        // 256 threads, one row each
    const float* M2b = g_M2 + (size_t)bh * Ll * Ll;
    const float* row = M2b + (size_t)t * Ll;
    float rs = 0.f;
    for (int j = 0; j < Ll; j++) rs += fabsf(row[j]);
    __shared__ float red[256];
    red[t] = rs;
    __syncthreads();
    for (int s = 128; s > 0; s >>= 1) {
        if (t < s) red[t] = fmaxf(red[t], red[t + s]);
        __syncthreads();
    }
    float nrm = red[0];
    float scale = 1.0f / (nrm * nrm + 1e-6f);
    float* inv = g_invA + (size_t)bh * Ll * Ll;
    for (int idx = t; idx < Ll * Ll; idx += 256) {
        int i = idx / Ll, j = idx % Ll;
        inv[idx] = M2b[(size_t)j * Ll + i] * scale;
    }
}

__global__ void ycls_kernel()
{
    int bh = blockIdx.x;
    int t  = threadIdx.x;        // 256 threads
    __shared__ float sc[Ll];
    __shared__ float qc[Dd];
    if (t < Dd) qc[t] = g_q[(size_t)bh * NT * Dd + t];
    __syncthreads();
    const float* kl = g_kland + ((size_t)bh * Ll + t) * Dd;
    float dot = 0.f;
#pragma unroll
    for (int d = 0; d < Dd; d++) dot += qc[d] * kl[d];
    float dist = g_qcn[bh] + g_kln[(size_t)bh * Ll + t] - 2.0f * dot;
    sc[t] = expf(dist * NEG_INV_TAU);
    __syncthreads();
    if (t < Dd) {
        float s = 0.f;
        for (int l = 0; l < Ll; l++)
            s += sc[l] * g_Vmix[((size_t)bh * Ll + l) * Dd + t];
        int b = bh / Hh, h = bh % Hh;
        g_attn[(size_t)b * NT * Cd + h * Dd + t] = s;
    }
}

// ---------------------------------------------------------------------------
// Host launcher
// ---------------------------------------------------------------------------
extern "C" void kernel_launch(void* const* d_in, const int* in_sizes, int n_in,
                              void* d_out, int out_size)
{
    (void)in_sizes; (void)n_in; (void)out_size;
    const float* x      = (const float*)d_in[0];
    const float* qkv_w  = (const float*)d_in[1];
    const float* qkv_b  = (const float*)d_in[2];
    const float* proj_w = (const float*)d_in[3];
    const float* proj_b = (const float*)d_in[4];
    float* out = (float*)d_out;

    float *p_q, *p_k, *p_v, *p_qland, *p_kland;
    float *p_qpn, *p_kpn, *p_qln, *p_kln;
    float *p_M1, *p_M2, *p_M3, *p_invA, *p_invB, *p_T, *p_KV, *p_Vmix, *p_attn;
    cudaGetSymbolAddress((void**)&p_q, g_q);
    cudaGetSymbolAddress((void**)&p_k, g_k);
    cudaGetSymbolAddress((void**)&p_v, g_v);
    cudaGetSymbolAddress((void**)&p_qland, g_qland);
    cudaGetSymbolAddress((void**)&p_kland, g_kland);
    cudaGetSymbolAddress((void**)&p_qpn, g_qpn);
    cudaGetSymbolAddress((void**)&p_kpn, g_kpn);
    cudaGetSymbolAddress((void**)&p_qln, g_qln);
    cudaGetSymbolAddress((void**)&p_kln, g_kln);
    cudaGetSymbolAddress((void**)&p_M1, g_M1);
    cudaGetSymbolAddress((void**)&p_M2, g_M2);
    cudaGetSymbolAddress((void**)&p_M3, g_M3);
    cudaGetSymbolAddress((void**)&p_invA, g_invA);
    cudaGetSymbolAddress((void**)&p_invB, g_invB);
    cudaGetSymbolAddress((void**)&p_T, g_T);
    cudaGetSymbolAddress((void**)&p_KV, g_KV);
    cudaGetSymbolAddress((void**)&p_Vmix, g_Vmix);
    cudaGetSymbolAddress((void**)&p_attn, g_attn);

    const int M_tok = Bn * NT;   // 16400
    const int gy_tok = (M_tok + 127) / 128;

    // 1. QKV projection: x @ qkv_w^T + b, scattered into q/k/v [B][H][N][D]
    {
        EpiQKV epi{qkv_b};
        dim3 grid(3 * Cd / 128, gy_tok, 1);
        gemm_tc<128, 128, true><<<grid, 256>>>(
            x, qkv_w, M_tok, 3 * Cd, Cd, Cd, Cd, 0, 0, epi);
    }

    // 2. pooling + norms
    pool_kernel<<<(BH * Ll * Dd + 255) / 256, 256>>>();
    norms_patch_kernel<<<(BH * NP + 255) / 256, 256>>>();
    norms_land_kernel<<<(BH * Ll + 255) / 256, 256>>>();

    // 3. Gauss kernel matrices
    {   // M2 = gauss(q_land, k_land): [L x L]
        EpiGauss epi{p_qln, p_kln, p_M2, Ll, Ll, Ll, (size_t)Ll * Ll};
        dim3 grid(Ll / 128, Ll / 128, BH);
        gemm_tc<128, 128, true><<<grid, 256>>>(
            p_qland, p_kland, Ll, Ll, Dd, Dd, Dd,
            (size_t)Ll * Dd, (size_t)Ll * Dd, epi);
    }
    {   // M1 = gauss(q_patch, k_land): [NP x L]
        EpiGauss epi{p_qpn, p_kln, p_M1, NP, Ll, Ll, (size_t)NP * Ll};
        dim3 grid(Ll / 128, NP / 128, BH);
        gemm_tc<128, 128, true><<<grid, 256>>>(
            p_q + Dd, p_kland, NP, Ll, Dd, Dd, Dd,
            (size_t)NT * Dd, (size_t)Ll * Dd, epi);
    }
    {   // M3 = gauss(q_land, k_patch): [L x NP]
        EpiGauss epi{p_qln, p_kpn, p_M3, Ll, NP, NP, (size_t)Ll * NP};
        dim3 grid(NP / 128, Ll / 128, BH);
        gemm_tc<128, 128, true><<<grid, 256>>>(
            p_qland, p_k + Dd, Ll, NP, Dd, Dd, Dd,
            (size_t)Ll * Dd, (size_t)NT * Dd, epi);
    }

    // 4. Newton iterations for M2^-1
    newton_init_kernel<<<BH, 256>>>();
    {
        float* cur = p_invA;
        float* nxt = p_invB;
        dim3 grid(Ll / 128, Ll / 128, BH);
        for (int it = 0; it < NEWTON_ITERS; it++) {
            EpiPlain epiT{p_T, Ll, (size_t)Ll * Ll};
            gemm_tc<128, 128, false><<<grid, 256>>>(
                p_M2, cur, Ll, Ll, Ll, Ll, Ll,
                (size_t)Ll * Ll, (size_t)Ll * Ll, epiT);
            EpiNewton epiN{cur, nxt};
            gemm_tc<128, 128, false><<<grid, 256>>>(
                cur, p_T, Ll, Ll, Ll, Ll, Ll,
                (size_t)Ll * Ll, (size_t)Ll * Ll, epiN);
            float* tmp = cur; cur = nxt; nxt = tmp;
        }
        // NEWTON_ITERS even -> result in p_invA
    }

    // 5. KV = M3 @ v_patch : [L x D]
    {
        EpiPlain epi{p_KV, Dd, (size_t)Ll * Dd};
        dim3 grid(1, Ll / 128, BH);
        gemm_tc<128, 64, false><<<grid, 128>>>(
            p_M3, p_v + Dd, Ll, Dd, NP, NP, Dd,
            (size_t)Ll * NP, (size_t)NT * Dd, epi);
    }
    // 6. V_mixed = M2_inv @ KV : [L x D]
    {
        EpiPlain epi{p_Vmix, Dd, (size_t)Ll * Dd};
        dim3 grid(1, Ll / 128, BH);
        gemm_tc<128, 64, false><<<grid, 128>>>(
            p_invA, p_KV, Ll, Dd, Ll, Ll, Dd,
            (size_t)Ll * Ll, (size_t)Ll * Dd, epi);
    }
    // 7. y_patch = M1 @ V_mixed -> attn[b][1..1024][h*64+d]
    {
        EpiYPatch epi{};
        dim3 grid(1, NP / 128, BH);
        gemm_tc<128, 64, false><<<grid, 128>>>(
            p_M1, p_Vmix, NP, Dd, Ll, Ll, Dd,
            (size_t)NP * Ll, (size_t)Ll * Dd, epi);
    }
    // 8. y_cls -> attn[b][0][h*64+d]
    ycls_kernel<<<BH, 256>>>();

    // 9. output projection: attn @ proj_w^T + proj_b
    {
        EpiProj epi{proj_b, out};
        dim3 grid(Cd / 128, gy_tok, 1);
        gemm_tc<128, 128, true><<<grid, 256>>>(
            p_attn, proj_w, M_tok, Cd, Cd, Cd, Cd, 0, 0, epi);
    }
}